// round 2
// baseline (speedup 1.0000x reference)
#include <cuda_runtime.h>
#include <cstdint>

#define N_NODES 100000
#define N_EDGES 1600000
#define D_FEAT  64

// Persistent scratch (no allocations allowed in kernel_launch).
__device__ float g_agg[N_NODES * D_FEAT];   // segment-sum accumulator
__device__ float g_h1 [N_NODES * D_FEAT];   // layer-1 output
__device__ float g_deg[N_NODES];            // in-degree per node

// ---------------------------------------------------------------------------
// Packed f32x2 helpers (B300: scalar FFMA rt=2/SMSP; f32x2 doubles throughput)
// ---------------------------------------------------------------------------
__device__ __forceinline__ double ffma2(double a, double b, double c) {
    double d;
    asm("fma.rn.f32x2 %0, %1, %2, %3;" : "=d"(d) : "d"(a), "d"(b), "d"(c));
    return d;
}
__device__ __forceinline__ double bcast2(float x) {
    double r;
    asm("mov.b64 %0, {%1, %1};" : "=d"(r) : "f"(x));
    return r;
}
__device__ __forceinline__ void unpack2(double v, float& lo, float& hi) {
    asm("mov.b64 {%0, %1}, %2;" : "=f"(lo), "=f"(hi) : "d"(v));
}

// ---------------------------------------------------------------------------
// Zero the aggregation buffer (and degree buffer on the first pass).
// ---------------------------------------------------------------------------
__global__ void zero_kernel(int with_deg) {
    int i = blockIdx.x * blockDim.x + threadIdx.x;
    if (i < N_NODES * (D_FEAT / 4)) {
        ((float4*)g_agg)[i] = make_float4(0.f, 0.f, 0.f, 0.f);
    }
    if (with_deg && i < N_NODES) {
        g_deg[i] = 0.f;
    }
}

// ---------------------------------------------------------------------------
// Degree: one float atomic per edge (REDG, no return).
// ---------------------------------------------------------------------------
__global__ void deg_kernel(const int* __restrict__ dst) {
    int e = blockIdx.x * blockDim.x + threadIdx.x;
    if (e < N_EDGES) {
        atomicAdd(&g_deg[dst[e]], 1.0f);
    }
}

// ---------------------------------------------------------------------------
// Edge-parallel aggregation: 16 lanes per edge, each lane moves one float4.
// ---------------------------------------------------------------------------
template <bool LAYER1>
__global__ void agg_kernel(const float4* __restrict__ xin,
                           const int* __restrict__ src,
                           const int* __restrict__ dst) {
    const float4* x4 = LAYER1 ? xin : (const float4*)g_h1;
    int i = blockIdx.x * blockDim.x + threadIdx.x;
    int e = i >> 4;
    int c = i & 15;
    if (e < N_EDGES) {
        int s = __ldg(&src[e]);
        int d = __ldg(&dst[e]);
        float4 v = __ldg(&x4[s * 16 + c]);
        float* p = (float*)&(((float4*)g_agg)[d * 16 + c]);
        asm volatile("red.global.add.v4.f32 [%0], {%1,%2,%3,%4};"
                     :: "l"(p), "f"(v.x), "f"(v.y), "f"(v.z), "f"(v.w)
                     : "memory");
    }
}

// ---------------------------------------------------------------------------
// Fused layer: out = act( X @ Wself^T + (agg/max(deg,1)) @ Wneigh^T + b )
// 64x64 tile per 64-thread CTA; 8x8 per thread; f32x2 packed FFMA along cols.
// Two K-phases (self, neigh) sharing the same accumulators.
// ---------------------------------------------------------------------------
template <bool LAYER1>
__global__ void __launch_bounds__(64)
sage_gemm(const float* __restrict__ Xin,
          const float* __restrict__ Wself,
          const float* __restrict__ Wneigh,
          const float* __restrict__ bias,
          float* __restrict__ outp) {
    const float* X   = LAYER1 ? Xin : (const float*)g_h1;
    float*       out = LAYER1 ? (float*)g_h1 : outp;

    __shared__ float sW[64 * 64];   // sW[k*64 + j] = W[j][k]
    __shared__ float sA[64 * 65];   // sA[r*65 + k], pad 65 -> a-frag bank-free
    __shared__ float sRinv[64];

    const int tid  = threadIdx.x;   // 0..63
    const int row0 = blockIdx.x * 64;
    const int tx   = tid & 7;       // col group: cols tx*8 .. tx*8+7
    const int ty   = tid >> 3;      // row group: rows ty*8 .. ty*8+7

    {
        int r = row0 + tid;
        float dg = (r < N_NODES) ? g_deg[r] : 1.0f;
        sRinv[tid] = 1.0f / fmaxf(dg, 1.0f);
    }

    // 8 rows x 4 f32x2-pairs (= 8 cols) of accumulators
    double acc[8][4];
#pragma unroll
    for (int i = 0; i < 8; i++)
#pragma unroll
        for (int j = 0; j < 4; j++) acc[i][j] = 0.0;   // bits(0,0) = {0.f,0.f}

#pragma unroll 1
    for (int ph = 0; ph < 2; ph++) {
        __syncthreads();   // protect sW/sA reuse across phases (and sRinv)

        // Load W transposed: thread tid streams row j=tid of W (contiguous,
        // L1-friendly); STS row l*64+tid is conflict-free.
        const float* W = (ph == 0) ? Wself : Wneigh;
#pragma unroll 8
        for (int l = 0; l < 64; l++) {
            sW[l * 64 + tid] = __ldg(&W[tid * 64 + l]);
        }

        // Load A tile (64 rows x 16 float4), scaled by 1/deg in phase 1.
        const float4* src4 = (ph == 0) ? (const float4*)X : (const float4*)g_agg;
#pragma unroll
        for (int l = 0; l < 16; l++) {
            int idx = tid + l * 64;          // 0..1023
            int r = idx >> 4, f = idx & 15;
            int gr = row0 + r;
            float4 v = make_float4(0.f, 0.f, 0.f, 0.f);
            if (gr < N_NODES) v = __ldg(&src4[gr * 16 + f]);
            if (ph == 1) {
                float s = sRinv[r];
                v.x *= s; v.y *= s; v.z *= s; v.w *= s;
            }
            float* p = sA + r * 65 + f * 4;  // pad-65: scalar stores
            p[0] = v.x; p[1] = v.y; p[2] = v.z; p[3] = v.w;
        }
        __syncthreads();

        // MAC loop: per k, 2x 16B b-frag loads + 8 broadcast a-frag LDS.32,
        // 32 packed FFMA2 (= 64 FMA lanes).
#pragma unroll 4
        for (int k = 0; k < 64; k++) {
            const double2 bb0 = *(const double2*)(sW + k * 64 + tx * 8);
            const double2 bb1 = *(const double2*)(sW + k * 64 + tx * 8 + 4);
#pragma unroll
            for (int i = 0; i < 8; i++) {
                double a2 = bcast2(sA[(ty * 8 + i) * 65 + k]);
                acc[i][0] = ffma2(a2, bb0.x, acc[i][0]);
                acc[i][1] = ffma2(a2, bb0.y, acc[i][1]);
                acc[i][2] = ffma2(a2, bb1.x, acc[i][2]);
                acc[i][3] = ffma2(a2, bb1.y, acc[i][3]);
            }
        }
    }

    // Epilogue: + bias, optional ReLU, store 2x float4 per row.
    const float4* b4 = (const float4*)bias;
    float4 bv0 = __ldg(&b4[tx * 2]);
    float4 bv1 = __ldg(&b4[tx * 2 + 1]);
#pragma unroll
    for (int i = 0; i < 8; i++) {
        int gr = row0 + ty * 8 + i;
        if (gr < N_NODES) {
            float o[8];
            unpack2(acc[i][0], o[0], o[1]);
            unpack2(acc[i][1], o[2], o[3]);
            unpack2(acc[i][2], o[4], o[5]);
            unpack2(acc[i][3], o[6], o[7]);
            o[0] += bv0.x; o[1] += bv0.y; o[2] += bv0.z; o[3] += bv0.w;
            o[4] += bv1.x; o[5] += bv1.y; o[6] += bv1.z; o[7] += bv1.w;
            if (LAYER1) {
#pragma unroll
                for (int j = 0; j < 8; j++) o[j] = fmaxf(o[j], 0.f);
            }
            float4* op = (float4*)(out + gr * 64 + tx * 8);
            op[0] = make_float4(o[0], o[1], o[2], o[3]);
            op[1] = make_float4(o[4], o[5], o[6], o[7]);
        }
    }
}

// ---------------------------------------------------------------------------
// Launch: zero -> deg -> agg1 -> layer1(relu) -> zero -> agg2 -> layer2
// ---------------------------------------------------------------------------
extern "C" void kernel_launch(void* const* d_in, const int* in_sizes, int n_in,
                              void* d_out, int out_size) {
    const float* in_feat = (const float*)d_in[0];
    const int*   src     = (const int*)d_in[1];
    const int*   dst     = (const int*)d_in[2];
    const float* Ws1     = (const float*)d_in[3];
    const float* Wn1     = (const float*)d_in[4];
    const float* b1      = (const float*)d_in[5];
    const float* Ws2     = (const float*)d_in[6];
    const float* Wn2     = (const float*)d_in[7];
    const float* b2      = (const float*)d_in[8];
    float*       out     = (float*)d_out;

    const int zero_blocks = (N_NODES * (D_FEAT / 4) + 255) / 256;
    const int deg_blocks  = (N_EDGES + 255) / 256;
    const int agg_blocks  = (N_EDGES * 16) / 256;
    const int gemm_blocks = (N_NODES + 63) / 64;    // 1563

    zero_kernel<<<zero_blocks, 256>>>(1);
    deg_kernel<<<deg_blocks, 256>>>(dst);
    agg_kernel<true><<<agg_blocks, 256>>>((const float4*)in_feat, src, dst);
    sage_gemm<true><<<gemm_blocks, 64>>>(in_feat, Ws1, Wn1, b1, nullptr);
    zero_kernel<<<zero_blocks, 256>>>(0);
    agg_kernel<false><<<agg_blocks, 256>>>(nullptr, src, dst);
    sage_gemm<false><<<gemm_blocks, 64>>>(nullptr, Ws2, Wn2, b2, out);
}

// round 3
// speedup vs baseline: 2.4367x; 2.4367x over previous
#include <cuda_runtime.h>
#include <cstdint>

#define N_NODES 100000
#define N_EDGES 1600000
#define NB_SCAN 196            // ceil(100000/512)

// Persistent scratch
__device__ float g_agg[N_NODES * 64];
__device__ float g_h1 [N_NODES * 64];
__device__ int   g_degi[N_NODES];
__device__ int   g_rowptr[N_NODES + 1];
__device__ int   g_cursor[N_NODES];
__device__ int   g_esrc[N_EDGES];
__device__ int   g_bsum[NB_SCAN];
__device__ int   g_bpre[NB_SCAN];

// ---------------- f32x2 helpers ----------------
__device__ __forceinline__ double ffma2(double a, double b, double c) {
    double d;
    asm("fma.rn.f32x2 %0, %1, %2, %3;" : "=d"(d) : "d"(a), "d"(b), "d"(c));
    return d;
}
__device__ __forceinline__ double add2(double a, double b) {
    double d;
    asm("add.rn.f32x2 %0, %1, %2;" : "=d"(d) : "d"(a), "d"(b));
    return d;
}
__device__ __forceinline__ void unpack2(double v, float& lo, float& hi) {
    asm("mov.b64 {%0, %1}, %2;" : "=f"(lo), "=f"(hi) : "d"(v));
}

// ---------------- CSR build ----------------
__global__ void csr_zero() {
    int i = blockIdx.x * blockDim.x + threadIdx.x;
    if (i < N_NODES) g_degi[i] = 0;
}

__global__ void csr_hist(const int* __restrict__ dst) {
    int e = blockIdx.x * blockDim.x + threadIdx.x;
    if (e < N_EDGES) atomicAdd(&g_degi[dst[e]], 1);
}

__global__ void scan_block() {                       // per-block sums
    __shared__ int sh[512];
    int t = threadIdx.x;
    int idx = blockIdx.x * 512 + t;
    int v = (idx < N_NODES) ? g_degi[idx] : 0;
    sh[t] = v;
    __syncthreads();
    for (int off = 256; off > 0; off >>= 1) {
        if (t < off) sh[t] += sh[t + off];
        __syncthreads();
    }
    if (t == 0) g_bsum[blockIdx.x] = sh[0];
}

__global__ void scan_top() {                         // exclusive scan of 196 sums
    __shared__ int sh[256];
    int t = threadIdx.x;
    int v = (t < NB_SCAN) ? g_bsum[t] : 0;
    sh[t] = v;
    __syncthreads();
    for (int off = 1; off < 256; off <<= 1) {
        int x = (t >= off) ? sh[t - off] : 0;
        __syncthreads();
        sh[t] += x;
        __syncthreads();
    }
    if (t < NB_SCAN) g_bpre[t] = sh[t] - v;          // exclusive
}

__global__ void scan_write() {                       // rowptr + cursor
    __shared__ int sh[512];
    int t = threadIdx.x;
    int idx = blockIdx.x * 512 + t;
    int v = (idx < N_NODES) ? g_degi[idx] : 0;
    sh[t] = v;
    __syncthreads();
    for (int off = 1; off < 512; off <<= 1) {
        int x = (t >= off) ? sh[t - off] : 0;
        __syncthreads();
        sh[t] += x;
        __syncthreads();
    }
    int excl = sh[t] - v + g_bpre[blockIdx.x];
    if (idx < N_NODES) {
        g_rowptr[idx] = excl;
        g_cursor[idx] = excl;
    }
    if (blockIdx.x == 0 && t == 0) g_rowptr[N_NODES] = N_EDGES;
}

__global__ void csr_scatter(const int* __restrict__ src,
                            const int* __restrict__ dst) {
    int e = blockIdx.x * blockDim.x + threadIdx.x;
    if (e < N_EDGES) {
        int p = atomicAdd(&g_cursor[dst[e]], 1);
        g_esrc[p] = src[e];
    }
}

// ---------------- Mean aggregation via CSR gather ----------------
// Warp handles 2 nodes (16 lanes each); lane owns one float4 feature chunk.
template <bool LAYER1>
__global__ void agg_csr(const float4* __restrict__ xin) {
    const float4* x4 = LAYER1 ? xin : (const float4*)g_h1;
    int gw   = (blockIdx.x * blockDim.x + threadIdx.x) >> 5;
    int lane = threadIdx.x & 31;
    int n = gw * 2 + (lane >> 4);
    int c = lane & 15;
    if (n >= N_NODES) return;
    int b = __ldg(&g_rowptr[n]);
    int e = __ldg(&g_rowptr[n + 1]);
    float4 a0 = make_float4(0.f, 0.f, 0.f, 0.f);
    float4 a1 = make_float4(0.f, 0.f, 0.f, 0.f);
    int i = b;
    for (; i + 1 < e; i += 2) {
        int s0 = __ldg(&g_esrc[i]);
        int s1 = __ldg(&g_esrc[i + 1]);
        float4 v0 = __ldg(&x4[s0 * 16 + c]);
        float4 v1 = __ldg(&x4[s1 * 16 + c]);
        a0.x += v0.x; a0.y += v0.y; a0.z += v0.z; a0.w += v0.w;
        a1.x += v1.x; a1.y += v1.y; a1.z += v1.z; a1.w += v1.w;
    }
    if (i < e) {
        int s0 = __ldg(&g_esrc[i]);
        float4 v0 = __ldg(&x4[s0 * 16 + c]);
        a0.x += v0.x; a0.y += v0.y; a0.z += v0.z; a0.w += v0.w;
    }
    int deg = e - b;
    float inv = 1.0f / (float)(deg > 0 ? deg : 1);
    float4 o;
    o.x = (a0.x + a1.x) * inv;
    o.y = (a0.y + a1.y) * inv;
    o.z = (a0.z + a1.z) * inv;
    o.w = (a0.w + a1.w) * inv;
    ((float4*)g_agg)[n * 16 + c] = o;
}

// ---------------- Fused layer GEMM ----------------
// out = act( X @ Ws^T + agg @ Wn^T + b ), agg already mean-normalized.
// CTA: 512 thr = 16 warps = 8 rowgroups x 2 k-halves. Tile 64 rows x 64 cols.
// Lane owns cols {lane, lane+32}; W held in regs as k-pair doubles (f32x2).
// acc double = {sum over even k, sum over odd k}; reduced in epilogue.
#define SW_PITCH 68   // floats; 272B rows -> 16B aligned, mild bank conflicts

template <bool LAYER1>
__global__ void __launch_bounds__(512, 1)
sage_gemm(const float* __restrict__ Xin,
          const float* __restrict__ Wself,
          const float* __restrict__ Wneigh,
          const float* __restrict__ bias,
          float* __restrict__ outp) {
    const float* X   = LAYER1 ? Xin : (const float*)g_h1;
    float*       out = LAYER1 ? (float*)g_h1 : outp;

    __shared__ __align__(16) float sA[64 * 64];      // 16 KB A tile
    __shared__ __align__(16) char  buf[32768];       // sW stage / epilogue red

    const int tid  = threadIdx.x;
    const int w    = tid >> 5;
    const int lane = tid & 31;
    const int h    = w & 1;          // k-half: k in [32h, 32h+32)
    const int rg   = w >> 1;         // rowgroup: rows rg*8 .. rg*8+7
    const int row0 = blockIdx.x * 64;
    const int c0   = lane;
    const int c1   = lane + 32;

    const float b0 = bias[c0];
    const float b1 = bias[c1];

    double acc0[8], acc1[8];
#pragma unroll
    for (int r = 0; r < 8; r++) { acc0[r] = 0.0; acc1[r] = 0.0; }

#pragma unroll 1
    for (int ph = 0; ph < 2; ph++) {
        __syncthreads();  // previous phase's sA/buf reads complete

        // Stage W into buf (coalesced), pitch SW_PITCH.
        const float* Wp = (ph == 0) ? Wself : Wneigh;
        float* sW = (float*)buf;
#pragma unroll
        for (int l = 0; l < 8; l++) {
            int i = tid + l * 512;               // 0..4095
            int j = i >> 6, k = i & 63;
            sW[j * SW_PITCH + k] = __ldg(&Wp[i]);
        }

        // Stage A tile (64 rows x 16 float4), zero-filled past N.
        const float4* S = (ph == 0) ? (const float4*)X : (const float4*)g_agg;
#pragma unroll
        for (int l = 0; l < 2; l++) {
            int i = tid + l * 512;               // 0..1023
            int r = i >> 4, f = i & 15;
            int gr = row0 + r;
            float4 v = make_float4(0.f, 0.f, 0.f, 0.f);
            if (gr < N_NODES) v = __ldg(&S[gr * 16 + f]);
            ((float4*)sA)[r * 16 + f] = v;
        }
        __syncthreads();

        // Pull this lane's W slice into registers (k-pair packed doubles).
        double w2a[16], w2b[16];
        {
            const double2* pa = (const double2*)(sW + c0 * SW_PITCH + h * 32);
            const double2* pb = (const double2*)(sW + c1 * SW_PITCH + h * 32);
#pragma unroll
            for (int kq = 0; kq < 8; kq++) {
                double2 ta = pa[kq];
                double2 tb = pb[kq];
                w2a[2 * kq] = ta.x; w2a[2 * kq + 1] = ta.y;
                w2b[2 * kq] = tb.x; w2b[2 * kq + 1] = tb.y;
            }
        }

        // MAC: per (row, k-quad): 1 uniform LDS.128 + 4 FFMA2.
#pragma unroll
        for (int r = 0; r < 8; r++) {
            const double2* ap = (const double2*)(sA + (rg * 8 + r) * 64 + h * 32);
#pragma unroll
            for (int kq = 0; kq < 8; kq++) {
                double2 a = ap[kq];
                acc0[r] = ffma2(a.x, w2a[2 * kq],     acc0[r]);
                acc0[r] = ffma2(a.y, w2a[2 * kq + 1], acc0[r]);
                acc1[r] = ffma2(a.x, w2b[2 * kq],     acc1[r]);
                acc1[r] = ffma2(a.y, w2b[2 * kq + 1], acc1[r]);
            }
        }
    }

    // Epilogue: combine k-halves via shared, then lo+hi, bias, relu, store.
    __syncthreads();                 // all MAC reads of buf (sW) done
    double* dRed = (double*)buf;     // 64 rows x 64 cols doubles? only 8x8x64
    if (h == 1) {
#pragma unroll
        for (int r = 0; r < 8; r++) {
            dRed[(rg * 8 + r) * 64 + c0] = acc0[r];
            dRed[(rg * 8 + r) * 64 + c1] = acc1[r];
        }
    }
    __syncthreads();
    if (h == 0) {
#pragma unroll
        for (int r = 0; r < 8; r++) {
            int gr = row0 + rg * 8 + r;
            if (gr < N_NODES) {
                double t0 = add2(acc0[r], dRed[(rg * 8 + r) * 64 + c0]);
                double t1 = add2(acc1[r], dRed[(rg * 8 + r) * 64 + c1]);
                float l0, h0, l1, h1;
                unpack2(t0, l0, h0);
                unpack2(t1, l1, h1);
                float o0 = l0 + h0 + b0;
                float o1 = l1 + h1 + b1;
                if (LAYER1) { o0 = fmaxf(o0, 0.f); o1 = fmaxf(o1, 0.f); }
                out[gr * 64 + c0] = o0;
                out[gr * 64 + c1] = o1;
            }
        }
    }
}

// Note: buf is 32KB = 4096 doubles; dRed uses (63*64+63) max index = 4095. OK.

// ---------------- Launch ----------------
extern "C" void kernel_launch(void* const* d_in, const int* in_sizes, int n_in,
                              void* d_out, int out_size) {
    const float* in_feat = (const float*)d_in[0];
    const int*   src     = (const int*)d_in[1];
    const int*   dst     = (const int*)d_in[2];
    const float* Ws1     = (const float*)d_in[3];
    const float* Wn1     = (const float*)d_in[4];
    const float* b1      = (const float*)d_in[5];
    const float* Ws2     = (const float*)d_in[6];
    const float* Wn2     = (const float*)d_in[7];
    const float* b2      = (const float*)d_in[8];
    float*       out     = (float*)d_out;

    const int e_blocks   = (N_EDGES + 255) / 256;        // 6250
    const int agg_blocks = ((N_NODES + 1) / 2 * 32 + 255) / 256;  // 6250
    const int gemm_blocks = (N_NODES + 63) / 64;         // 1563

    // CSR build (per launch; deterministic up to edge ordering, sums commute)
    csr_zero<<<(N_NODES + 1023) / 1024, 1024>>>();
    csr_hist<<<e_blocks, 256>>>(dst);
    scan_block<<<NB_SCAN, 512>>>();
    scan_top<<<1, 256>>>();
    scan_write<<<NB_SCAN, 512>>>();
    csr_scatter<<<e_blocks, 256>>>(src, dst);

    // Layer 1
    agg_csr<true><<<agg_blocks, 256>>>((const float4*)in_feat);
    sage_gemm<true><<<gemm_blocks, 512>>>(in_feat, Ws1, Wn1, b1, nullptr);
    // Layer 2
    agg_csr<false><<<agg_blocks, 256>>>(nullptr);
    sage_gemm<false><<<gemm_blocks, 512>>>(nullptr, Ws2, Wn2, b2, out);
}